// round 6
// baseline (speedup 1.0000x reference)
#include <cuda_runtime.h>
#include <cstdint>

// ---------------------------------------------------------------------------
// CausalSelfAttention: B=4, S=2048, D=1024, fp32, causal softmax (scale 1/32)
// Staged: [round inputs] -> [proj x3] -> [scores lower-tri] -> [softmax] -> [PV]
// All GEMMs tf32 mma.sync m16n8k8, operands pre-rounded to tf32 at production.
// 4-stage cp.async pipeline, one barrier per k-iter (latency-covered mainloop).
// ---------------------------------------------------------------------------

#define BATCH 4
#define SEQ   2048
#define DIM   1024
#define NQT   (SEQ / 128)
#define NTRI  (NQT * (NQT + 1) / 2)   // 136 lower-tri tiles

__device__ float g_X [(size_t)BATCH * SEQ * DIM];
__device__ float g_Wq[(size_t)DIM * DIM];
__device__ float g_Wk[(size_t)DIM * DIM];
__device__ float g_Wv[(size_t)DIM * DIM];
__device__ float g_Q [(size_t)BATCH * SEQ * DIM];
__device__ float g_K [(size_t)BATCH * SEQ * DIM];
__device__ float g_V [(size_t)BATCH * SEQ * DIM];
__device__ float g_S [(size_t)BATCH * SEQ * SEQ];

// ---------------------------------------------------------------------------
__device__ __forceinline__ uint32_t f2tf32(float f) {
    uint32_t u;
    asm("cvt.rna.tf32.f32 %0, %1;" : "=r"(u) : "f"(f));
    return u;
}
__device__ __forceinline__ float roundtf(float f) {
    return __uint_as_float(f2tf32(f));
}

__device__ __forceinline__ void mma_tf32(float* d, const uint32_t* a,
                                         const uint32_t* b, const float* c) {
    asm volatile(
        "mma.sync.aligned.m16n8k8.row.col.f32.tf32.tf32.f32 "
        "{%0,%1,%2,%3}, {%4,%5,%6,%7}, {%8,%9}, {%10,%11,%12,%13};\n"
        : "=f"(d[0]), "=f"(d[1]), "=f"(d[2]), "=f"(d[3])
        : "r"(a[0]), "r"(a[1]), "r"(a[2]), "r"(a[3]),
          "r"(b[0]), "r"(b[1]),
          "f"(c[0]), "f"(c[1]), "f"(c[2]), "f"(c[3]));
}

__device__ __forceinline__ void cpa16(void* smem, const void* g) {
    uint32_t s = (uint32_t)__cvta_generic_to_shared(smem);
    asm volatile("cp.async.cg.shared.global [%0], [%1], 16;\n" :: "r"(s), "l"(g));
}
#define CP_COMMIT() asm volatile("cp.async.commit_group;\n")
#define CP_WAIT(n)  asm volatile("cp.async.wait_group %0;\n" :: "n"(n))

// ---------------------------------------------------------------------------
// 128x128 tile GEMM, 4-stage cp.async pipeline.
//   MODE 0: B stored [n][k] (k contig)  -> C = A @ B^T
//   MODE 1: B stored [k][n] (n contig)  -> C = A @ B
// ROUND 1: round C to tf32 on store.
// kIters >= STAGES-1 required (min here is 8).
// ---------------------------------------------------------------------------
template <int MODE, int ROUND>
__device__ __forceinline__ void gemm_core(const float* __restrict__ A,
                                          const float* __restrict__ Bm,
                                          float* __restrict__ C,
                                          int lda, int ldb, int ldc,
                                          int kIters, int row0, int col0) {
    constexpr int STAGES = 4;
    constexpr int BM = 128, BK = 16;
    constexpr int BROWS  = (MODE == 0) ? 128 : 16;
    constexpr int BCOLS  = (MODE == 0) ? 16  : 128;
    constexpr int BPAD   = (MODE == 0) ? 4   : 8;
    constexpr int ASTR   = BK + 4;      // 20
    constexpr int BSTR   = BCOLS + BPAD;

    extern __shared__ float sm[];
    float* Asm = sm;                                  // [STAGES][BM][ASTR]
    float* Bsm = sm + (size_t)STAGES * BM * ASTR;     // [STAGES][BROWS][BSTR]

    const int tid  = threadIdx.x;
    const int warp = tid >> 5;
    const int lane = tid & 31;
    const int wm   = (warp >> 2) * 64;
    const int wn   = (warp & 3) * 32;
    const int gid  = lane >> 2;
    const int tig  = lane & 3;

    float acc[4][4][4];
#pragma unroll
    for (int i = 0; i < 4; i++)
#pragma unroll
        for (int j = 0; j < 4; j++)
#pragma unroll
            for (int r = 0; r < 4; r++) acc[i][j][r] = 0.f;

    auto loadA = [&](int kt, int s) {
#pragma unroll
        for (int i = 0; i < 2; i++) {
            int f = tid + i * 256;
            int r = f >> 2, q = f & 3;
            cpa16(&Asm[(s * BM + r) * ASTR + q * 4],
                  &A[(size_t)(row0 + r) * lda + kt * BK + q * 4]);
        }
    };
    auto loadB = [&](int kt, int s) {
        if (MODE == 0) {
#pragma unroll
            for (int i = 0; i < 2; i++) {
                int f = tid + i * 256;
                int r = f >> 2, q = f & 3;
                cpa16(&Bsm[(s * BROWS + r) * BSTR + q * 4],
                      &Bm[(size_t)(col0 + r) * ldb + kt * BK + q * 4]);
            }
        } else {
#pragma unroll
            for (int i = 0; i < 2; i++) {
                int f = tid + i * 256;
                int r = f >> 5, q = f & 31;
                cpa16(&Bsm[(s * BROWS + r) * BSTR + q * 4],
                      &Bm[(size_t)(kt * BK + r) * ldb + col0 + q * 4]);
            }
        }
    };

    // prologue: stages 0..STAGES-2 (kIters >= STAGES-1 guaranteed)
#pragma unroll
    for (int p = 0; p < STAGES - 1; p++) {
        loadA(p, p);
        loadB(p, p);
        CP_COMMIT();
    }

    for (int kt = 0; kt < kIters; kt++) {
        // groups committed so far = kt + STAGES-1; wait => group kt complete
        CP_WAIT(STAGES - 2);
        __syncthreads();   // (a) all threads' tile-kt copies visible
                           // (b) all warps done with stage (kt-1)%STAGES
        {
            int nt = kt + STAGES - 1;
            if (nt < kIters) {
                loadA(nt, nt % STAGES);   // writes stage (kt-1)%STAGES: safe
                loadB(nt, nt % STAGES);
            }
            CP_COMMIT();  // commit every iter (empty groups keep count simple)
        }

        const int st = kt % STAGES;
#pragma unroll
        for (int ks = 0; ks < 2; ks++) {
            const int kk = ks * 8;
            uint32_t af[4][4];
#pragma unroll
            for (int mf = 0; mf < 4; mf++) {
                int r = wm + mf * 16 + gid;
                af[mf][0] = __float_as_uint(Asm[(st * BM + r) * ASTR + kk + tig]);
                af[mf][1] = __float_as_uint(Asm[(st * BM + r + 8) * ASTR + kk + tig]);
                af[mf][2] = __float_as_uint(Asm[(st * BM + r) * ASTR + kk + tig + 4]);
                af[mf][3] = __float_as_uint(Asm[(st * BM + r + 8) * ASTR + kk + tig + 4]);
            }
            uint32_t bf[4][2];
#pragma unroll
            for (int nf = 0; nf < 4; nf++) {
                int n = wn + nf * 8 + gid;
                if (MODE == 0) {
                    bf[nf][0] = __float_as_uint(Bsm[(st * BROWS + n) * BSTR + kk + tig]);
                    bf[nf][1] = __float_as_uint(Bsm[(st * BROWS + n) * BSTR + kk + tig + 4]);
                } else {
                    bf[nf][0] = __float_as_uint(Bsm[(st * BROWS + kk + tig) * BSTR + n]);
                    bf[nf][1] = __float_as_uint(Bsm[(st * BROWS + kk + tig + 4) * BSTR + n]);
                }
            }
#pragma unroll
            for (int mf = 0; mf < 4; mf++)
#pragma unroll
                for (int nf = 0; nf < 4; nf++)
                    mma_tf32(acc[mf][nf], af[mf], bf[nf], acc[mf][nf]);
        }
    }

#pragma unroll
    for (int mf = 0; mf < 4; mf++) {
#pragma unroll
        for (int nf = 0; nf < 4; nf++) {
            int r = row0 + wm + mf * 16 + gid;
            int c = col0 + wn + nf * 8 + tig * 2;
            float v0 = acc[mf][nf][0], v1 = acc[mf][nf][1];
            float v2 = acc[mf][nf][2], v3 = acc[mf][nf][3];
            if (ROUND) { v0 = roundtf(v0); v1 = roundtf(v1);
                         v2 = roundtf(v2); v3 = roundtf(v3); }
            C[(size_t)r * ldc + c]           = v0;
            C[(size_t)r * ldc + c + 1]       = v1;
            C[(size_t)(r + 8) * ldc + c]     = v2;
            C[(size_t)(r + 8) * ldc + c + 1] = v3;
        }
    }
}

// smem sizes (bytes)
#define SMEM_MODE0 (4 * (128 * 20 + 128 * 20) * 4)   // 81920
#define SMEM_MODE1 (4 * (128 * 20 + 16 * 136) * 4)   // 75776

// ---------------------------------------------------------------------------
// kernels
// ---------------------------------------------------------------------------
__global__ __launch_bounds__(256) void round_kernel(const float4* __restrict__ x,
                                                    const float4* __restrict__ wq,
                                                    const float4* __restrict__ wk,
                                                    const float4* __restrict__ wv) {
    const float4* src;
    float4* dst;
    int n4;
    switch (blockIdx.y) {
        case 0: src = x;  dst = (float4*)g_X;  n4 = BATCH * SEQ * DIM / 4; break;
        case 1: src = wq; dst = (float4*)g_Wq; n4 = DIM * DIM / 4; break;
        case 2: src = wk; dst = (float4*)g_Wk; n4 = DIM * DIM / 4; break;
        default: src = wv; dst = (float4*)g_Wv; n4 = DIM * DIM / 4; break;
    }
    for (int i = blockIdx.x * 256 + threadIdx.x; i < n4; i += gridDim.x * 256) {
        float4 v = src[i];
        v.x = roundtf(v.x); v.y = roundtf(v.y);
        v.z = roundtf(v.z); v.w = roundtf(v.w);
        dst[i] = v;
    }
}

__global__ __launch_bounds__(256) void proj_kernel() {
    const float* W = (blockIdx.z == 0) ? g_Wq : (blockIdx.z == 1) ? g_Wk : g_Wv;
    float* O = (blockIdx.z == 0) ? g_Q : (blockIdx.z == 1) ? g_K : g_V;
    gemm_core<0, 1>(g_X, W, O, DIM, DIM, DIM, DIM / 16,
                    blockIdx.y * 128, blockIdx.x * 128);
}

__device__ __forceinline__ void tri_decode(int t, int& qt, int& kt) {
    int q = (int)((sqrtf(8.0f * t + 1.0f) - 1.0f) * 0.5f);
    while ((q + 1) * (q + 2) / 2 <= t) q++;
    while (q * (q + 1) / 2 > t) q--;
    qt = q;
    kt = t - q * (q + 1) / 2;
}

__global__ __launch_bounds__(256) void scores_kernel() {
    int qt, kt;
    tri_decode(blockIdx.x, qt, kt);
    int b = blockIdx.z;
    const float* Qp = g_Q + (size_t)b * SEQ * DIM;
    const float* Kp = g_K + (size_t)b * SEQ * DIM;
    float* Sp = g_S + (size_t)b * SEQ * SEQ;
    gemm_core<0, 0>(Qp, Kp, Sp, DIM, DIM, SEQ, DIM / 16, qt * 128, kt * 128);
}

__global__ __launch_bounds__(256) void softmax_kernel() {
    const int row = blockIdx.x;
    const int b = row / SEQ, q = row % SEQ;
    float* p = g_S + (size_t)b * SEQ * SEQ + (size_t)q * SEQ;
    const int len  = q + 1;
    const int kend = ((q / 128) + 1) * 128;
    const float scale = 0.03125f;  // 1/sqrt(1024)

    __shared__ float red[8];
    __shared__ float red2[8];

    float vals[8];
    int cnt = 0;
    float m = -1e30f;
    for (int i = threadIdx.x; i < len; i += 256) {
        float v = p[i];
        vals[cnt++] = v;
        m = fmaxf(m, v);
    }
#pragma unroll
    for (int o = 16; o; o >>= 1) m = fmaxf(m, __shfl_xor_sync(~0u, m, o));
    if ((threadIdx.x & 31) == 0) red[threadIdx.x >> 5] = m;
    __syncthreads();
    m = red[0];
#pragma unroll
    for (int i = 1; i < 8; i++) m = fmaxf(m, red[i]);

    float s = 0.f;
#pragma unroll 8
    for (int j = 0; j < cnt; j++) {
        float e = __expf(scale * (vals[j] - m));
        vals[j] = e;
        s += e;
    }
#pragma unroll
    for (int o = 16; o; o >>= 1) s += __shfl_xor_sync(~0u, s, o);
    if ((threadIdx.x & 31) == 0) red2[threadIdx.x >> 5] = s;
    __syncthreads();
    s = 0.f;
#pragma unroll
    for (int i = 0; i < 8; i++) s += red2[i];
    const float inv = 1.0f / s;

    cnt = 0;
    for (int i = threadIdx.x; i < len; i += 256)
        p[i] = roundtf(vals[cnt++] * inv);
    for (int i = len + threadIdx.x; i < kend; i += 256) p[i] = 0.f;
}

__global__ __launch_bounds__(256) void pv_kernel(float* __restrict__ out) {
    int qt = blockIdx.y, et = blockIdx.x, b = blockIdx.z;
    const float* P = g_S + (size_t)b * SEQ * SEQ;
    const float* V = g_V + (size_t)b * SEQ * DIM;
    float* O = out + (size_t)b * SEQ * DIM;
    gemm_core<1, 0>(P, V, O, SEQ, DIM, DIM, (qt + 1) * 8, qt * 128, et * 128);
}

// ---------------------------------------------------------------------------
extern "C" void kernel_launch(void* const* d_in, const int* in_sizes, int n_in,
                              void* d_out, int out_size) {
    int xi = 0;
    for (int i = 0; i < n_in; i++)
        if (in_sizes[i] == BATCH * SEQ * DIM) { xi = i; break; }
    const float* x = (const float*)d_in[xi];
    const float* w[3];
    int wi = 0;
    for (int i = 0; i < n_in && wi < 3; i++)
        if (i != xi) w[wi++] = (const float*)d_in[i];
    float* out = (float*)d_out;

    // idempotent attribute sets (host-side state, not stream ops)
    cudaFuncSetAttribute(proj_kernel,
                         cudaFuncAttributeMaxDynamicSharedMemorySize, SMEM_MODE0);
    cudaFuncSetAttribute(scores_kernel,
                         cudaFuncAttributeMaxDynamicSharedMemorySize, SMEM_MODE0);
    cudaFuncSetAttribute(pv_kernel,
                         cudaFuncAttributeMaxDynamicSharedMemorySize, SMEM_MODE1);

    round_kernel<<<dim3(512, 4), 256>>>((const float4*)x, (const float4*)w[0],
                                        (const float4*)w[1], (const float4*)w[2]);
    proj_kernel<<<dim3(8, 64, 3), 256, SMEM_MODE0>>>();
    scores_kernel<<<dim3(NTRI, 1, 4), 256, SMEM_MODE0>>>();
    softmax_kernel<<<BATCH * SEQ, 256>>>();
    pv_kernel<<<dim3(8, 16, 4), 256, SMEM_MODE1>>>(out);
}

// round 9
// speedup vs baseline: 1.1705x; 1.1705x over previous
#include <cuda_runtime.h>
#include <cstdint>

// ---------------------------------------------------------------------------
// CausalSelfAttention: B=4, S=2048, D=1024, fp32, causal softmax (scale 1/32)
// Staged: [round inputs] -> [proj x3] -> [scores lower-tri] -> [softmax] -> [PV]
// tf32 mma.sync m16n8k8, pre-rounded operands, 128x128 CTA tile, BK=32,
// 2-stage cp.async double buffer (2 barriers per 32-k tile).
// ---------------------------------------------------------------------------

#define BATCH 4
#define SEQ   2048
#define DIM   1024
#define NQT   (SEQ / 128)
#define NTRI  (NQT * (NQT + 1) / 2)   // 136 lower-tri tiles

__device__ float g_X [(size_t)BATCH * SEQ * DIM];
__device__ float g_Wq[(size_t)DIM * DIM];
__device__ float g_Wk[(size_t)DIM * DIM];
__device__ float g_Wv[(size_t)DIM * DIM];
__device__ float g_Q [(size_t)BATCH * SEQ * DIM];
__device__ float g_K [(size_t)BATCH * SEQ * DIM];
__device__ float g_V [(size_t)BATCH * SEQ * DIM];
__device__ float g_S [(size_t)BATCH * SEQ * SEQ];

// ---------------------------------------------------------------------------
__device__ __forceinline__ uint32_t f2tf32(float f) {
    uint32_t u;
    asm("cvt.rna.tf32.f32 %0, %1;" : "=r"(u) : "f"(f));
    return u;
}
__device__ __forceinline__ float roundtf(float f) {
    return __uint_as_float(f2tf32(f));
}

__device__ __forceinline__ void mma_tf32(float* d, const uint32_t* a,
                                         const uint32_t* b, const float* c) {
    asm volatile(
        "mma.sync.aligned.m16n8k8.row.col.f32.tf32.tf32.f32 "
        "{%0,%1,%2,%3}, {%4,%5,%6,%7}, {%8,%9}, {%10,%11,%12,%13};\n"
        : "=f"(d[0]), "=f"(d[1]), "=f"(d[2]), "=f"(d[3])
        : "r"(a[0]), "r"(a[1]), "r"(a[2]), "r"(a[3]),
          "r"(b[0]), "r"(b[1]),
          "f"(c[0]), "f"(c[1]), "f"(c[2]), "f"(c[3]));
}

__device__ __forceinline__ void cpa16(void* smem, const void* g) {
    uint32_t s = (uint32_t)__cvta_generic_to_shared(smem);
    asm volatile("cp.async.cg.shared.global [%0], [%1], 16;\n" :: "r"(s), "l"(g));
}
#define CP_COMMIT() asm volatile("cp.async.commit_group;\n")
#define CP_WAIT(n)  asm volatile("cp.async.wait_group %0;\n" :: "n"(n))

// ---------------------------------------------------------------------------
// 128x128 tile GEMM, BK=32 (4 m16n8k8 k-steps/tile), 2-stage double buffer.
//   MODE 0: B stored [n][k] (k contig)  -> C = A @ B^T
//   MODE 1: B stored [k][n] (n contig)  -> C = A @ B
// ROUND 1: round C to tf32 on store.
// kIters = K / 32.
// ---------------------------------------------------------------------------
template <int MODE, int ROUND>
__device__ __forceinline__ void gemm_core(const float* __restrict__ A,
                                          const float* __restrict__ Bm,
                                          float* __restrict__ C,
                                          int lda, int ldb, int ldc,
                                          int kIters, int row0, int col0) {
    constexpr int BM = 128, BK = 32;
    constexpr int BROWS = (MODE == 0) ? 128 : 32;
    constexpr int BCOLS = (MODE == 0) ? 32  : 128;
    constexpr int BPAD  = (MODE == 0) ? 4   : 8;
    constexpr int ASTR  = BK + 4;        // 36
    constexpr int BSTR  = BCOLS + BPAD;  // 36 / 136

    extern __shared__ float sm[];
    float* Asm = sm;                               // [2][BM][ASTR]
    float* Bsm = sm + (size_t)2 * BM * ASTR;       // [2][BROWS][BSTR]

    const int tid  = threadIdx.x;
    const int warp = tid >> 5;
    const int lane = tid & 31;
    const int wm   = (warp >> 2) * 64;
    const int wn   = (warp & 3) * 32;
    const int gid  = lane >> 2;
    const int tig  = lane & 3;

    float acc[4][4][4];
#pragma unroll
    for (int i = 0; i < 4; i++)
#pragma unroll
        for (int j = 0; j < 4; j++)
#pragma unroll
            for (int r = 0; r < 4; r++) acc[i][j][r] = 0.f;

    auto loadA = [&](int kt, int buf) {
#pragma unroll
        for (int i = 0; i < 4; i++) {          // 128x32 = 1024 16B chunks
            int f = tid + i * 256;
            int r = f >> 3, q = f & 7;
            cpa16(&Asm[((buf * BM + r) * ASTR) + q * 4],
                  &A[(size_t)(row0 + r) * lda + kt * BK + q * 4]);
        }
    };
    auto loadB = [&](int kt, int buf) {
        if (MODE == 0) {
#pragma unroll
            for (int i = 0; i < 4; i++) {
                int f = tid + i * 256;
                int r = f >> 3, q = f & 7;     // r = n, q*4 = k
                cpa16(&Bsm[((buf * BROWS + r) * BSTR) + q * 4],
                      &Bm[(size_t)(col0 + r) * ldb + kt * BK + q * 4]);
            }
        } else {
#pragma unroll
            for (int i = 0; i < 4; i++) {
                int f = tid + i * 256;
                int r = f >> 5, q = f & 31;    // r = k (0..31), q*4 = n
                cpa16(&Bsm[((buf * BROWS + r) * BSTR) + q * 4],
                      &Bm[(size_t)(kt * BK + r) * ldb + col0 + q * 4]);
            }
        }
    };

    loadA(0, 0);
    loadB(0, 0);
    CP_COMMIT();

    int buf = 0;
    for (int kt = 0; kt < kIters; kt++) {
        if (kt + 1 < kIters) {
            loadA(kt + 1, buf ^ 1);
            loadB(kt + 1, buf ^ 1);
            CP_COMMIT();
            CP_WAIT(1);
        } else {
            CP_WAIT(0);
        }
        __syncthreads();

#pragma unroll
        for (int ks = 0; ks < 4; ks++) {
            const int kk = ks * 8;
            uint32_t af[4][4];
#pragma unroll
            for (int mf = 0; mf < 4; mf++) {
                int r = wm + mf * 16 + gid;
                af[mf][0] = __float_as_uint(Asm[(buf * BM + r) * ASTR + kk + tig]);
                af[mf][1] = __float_as_uint(Asm[(buf * BM + r + 8) * ASTR + kk + tig]);
                af[mf][2] = __float_as_uint(Asm[(buf * BM + r) * ASTR + kk + tig + 4]);
                af[mf][3] = __float_as_uint(Asm[(buf * BM + r + 8) * ASTR + kk + tig + 4]);
            }
            uint32_t bf[4][2];
#pragma unroll
            for (int nf = 0; nf < 4; nf++) {
                int n = wn + nf * 8 + gid;
                if (MODE == 0) {
                    bf[nf][0] = __float_as_uint(Bsm[(buf * BROWS + n) * BSTR + kk + tig]);
                    bf[nf][1] = __float_as_uint(Bsm[(buf * BROWS + n) * BSTR + kk + tig + 4]);
                } else {
                    bf[nf][0] = __float_as_uint(Bsm[(buf * BROWS + kk + tig) * BSTR + n]);
                    bf[nf][1] = __float_as_uint(Bsm[(buf * BROWS + kk + tig + 4) * BSTR + n]);
                }
            }
#pragma unroll
            for (int mf = 0; mf < 4; mf++)
#pragma unroll
                for (int nf = 0; nf < 4; nf++)
                    mma_tf32(acc[mf][nf], af[mf], bf[nf], acc[mf][nf]);
        }
        __syncthreads();
        buf ^= 1;
    }

#pragma unroll
    for (int mf = 0; mf < 4; mf++) {
#pragma unroll
        for (int nf = 0; nf < 4; nf++) {
            int r = row0 + wm + mf * 16 + gid;
            int c = col0 + wn + nf * 8 + tig * 2;
            float v0 = acc[mf][nf][0], v1 = acc[mf][nf][1];
            float v2 = acc[mf][nf][2], v3 = acc[mf][nf][3];
            if (ROUND) { v0 = roundtf(v0); v1 = roundtf(v1);
                         v2 = roundtf(v2); v3 = roundtf(v3); }
            C[(size_t)r * ldc + c]           = v0;
            C[(size_t)r * ldc + c + 1]       = v1;
            C[(size_t)(r + 8) * ldc + c]     = v2;
            C[(size_t)(r + 8) * ldc + c + 1] = v3;
        }
    }
}

// smem bytes
#define SMEM_MODE0 (2 * (128 * 36 + 128 * 36) * 4)   // 73728
#define SMEM_MODE1 (2 * (128 * 36 + 32 * 136) * 4)   // 71680

// ---------------------------------------------------------------------------
// kernels
// ---------------------------------------------------------------------------
__global__ __launch_bounds__(256) void round_kernel(const float4* __restrict__ x,
                                                    const float4* __restrict__ wq,
                                                    const float4* __restrict__ wk,
                                                    const float4* __restrict__ wv) {
    const float4* src;
    float4* dst;
    int n4;
    switch (blockIdx.y) {
        case 0: src = x;  dst = (float4*)g_X;  n4 = BATCH * SEQ * DIM / 4; break;
        case 1: src = wq; dst = (float4*)g_Wq; n4 = DIM * DIM / 4; break;
        case 2: src = wk; dst = (float4*)g_Wk; n4 = DIM * DIM / 4; break;
        default: src = wv; dst = (float4*)g_Wv; n4 = DIM * DIM / 4; break;
    }
    for (int i = blockIdx.x * 256 + threadIdx.x; i < n4; i += gridDim.x * 256) {
        float4 v = src[i];
        v.x = roundtf(v.x); v.y = roundtf(v.y);
        v.z = roundtf(v.z); v.w = roundtf(v.w);
        dst[i] = v;
    }
}

__global__ __launch_bounds__(256, 2) void proj_kernel() {
    const float* W = (blockIdx.z == 0) ? g_Wq : (blockIdx.z == 1) ? g_Wk : g_Wv;
    float* O = (blockIdx.z == 0) ? g_Q : (blockIdx.z == 1) ? g_K : g_V;
    gemm_core<0, 1>(g_X, W, O, DIM, DIM, DIM, DIM / 32,
                    blockIdx.y * 128, blockIdx.x * 128);
}

__device__ __forceinline__ void tri_decode(int t, int& qt, int& kt) {
    int q = (int)((sqrtf(8.0f * t + 1.0f) - 1.0f) * 0.5f);
    while ((q + 1) * (q + 2) / 2 <= t) q++;
    while (q * (q + 1) / 2 > t) q--;
    qt = q;
    kt = t - q * (q + 1) / 2;
}

__global__ __launch_bounds__(256, 2) void scores_kernel() {
    int qt, kt;
    tri_decode(blockIdx.x, qt, kt);
    int b = blockIdx.z;
    const float* Qp = g_Q + (size_t)b * SEQ * DIM;
    const float* Kp = g_K + (size_t)b * SEQ * DIM;
    float* Sp = g_S + (size_t)b * SEQ * SEQ;
    gemm_core<0, 0>(Qp, Kp, Sp, DIM, DIM, SEQ, DIM / 32, qt * 128, kt * 128);
}

__global__ __launch_bounds__(256) void softmax_kernel() {
    const int row = blockIdx.x;
    const int b = row / SEQ, q = row % SEQ;
    float* p = g_S + (size_t)b * SEQ * SEQ + (size_t)q * SEQ;
    const int len  = q + 1;
    const int kend = ((q / 128) + 1) * 128;
    const float scale = 0.03125f;  // 1/sqrt(1024)

    __shared__ float red[8];
    __shared__ float red2[8];

    float vals[8];
    int cnt = 0;
    float m = -1e30f;
    for (int i = threadIdx.x; i < len; i += 256) {
        float v = p[i];
        vals[cnt++] = v;
        m = fmaxf(m, v);
    }
#pragma unroll
    for (int o = 16; o; o >>= 1) m = fmaxf(m, __shfl_xor_sync(~0u, m, o));
    if ((threadIdx.x & 31) == 0) red[threadIdx.x >> 5] = m;
    __syncthreads();
    m = red[0];
#pragma unroll
    for (int i = 1; i < 8; i++) m = fmaxf(m, red[i]);

    float s = 0.f;
#pragma unroll 8
    for (int j = 0; j < cnt; j++) {
        float e = __expf(scale * (vals[j] - m));
        vals[j] = e;
        s += e;
    }
#pragma unroll
    for (int o = 16; o; o >>= 1) s += __shfl_xor_sync(~0u, s, o);
    if ((threadIdx.x & 31) == 0) red2[threadIdx.x >> 5] = s;
    __syncthreads();
    s = 0.f;
#pragma unroll
    for (int i = 0; i < 8; i++) s += red2[i];
    const float inv = 1.0f / s;

    cnt = 0;
    for (int i = threadIdx.x; i < len; i += 256)
        p[i] = roundtf(vals[cnt++] * inv);
    for (int i = len + threadIdx.x; i < kend; i += 256) p[i] = 0.f;
}

__global__ __launch_bounds__(256, 2) void pv_kernel(float* __restrict__ out) {
    int qt = blockIdx.y, et = blockIdx.x, b = blockIdx.z;
    const float* P = g_S + (size_t)b * SEQ * SEQ;
    const float* V = g_V + (size_t)b * SEQ * DIM;
    float* O = out + (size_t)b * SEQ * DIM;
    // causal: k range = (qt+1)*128 => kIters = (qt+1)*4 at BK=32
    gemm_core<1, 0>(P, V, O, SEQ, DIM, DIM, (qt + 1) * 4, qt * 128, et * 128);
}

// ---------------------------------------------------------------------------
extern "C" void kernel_launch(void* const* d_in, const int* in_sizes, int n_in,
                              void* d_out, int out_size) {
    int xi = 0;
    for (int i = 0; i < n_in; i++)
        if (in_sizes[i] == BATCH * SEQ * DIM) { xi = i; break; }
    const float* x = (const float*)d_in[xi];
    const float* w[3];
    int wi = 0;
    for (int i = 0; i < n_in && wi < 3; i++)
        if (i != xi) w[wi++] = (const float*)d_in[i];
    float* out = (float*)d_out;

    cudaFuncSetAttribute(proj_kernel,
                         cudaFuncAttributeMaxDynamicSharedMemorySize, SMEM_MODE0);
    cudaFuncSetAttribute(scores_kernel,
                         cudaFuncAttributeMaxDynamicSharedMemorySize, SMEM_MODE0);
    cudaFuncSetAttribute(pv_kernel,
                         cudaFuncAttributeMaxDynamicSharedMemorySize, SMEM_MODE1);

    round_kernel<<<dim3(512, 4), 256>>>((const float4*)x, (const float4*)w[0],
                                        (const float4*)w[1], (const float4*)w[2]);
    proj_kernel<<<dim3(8, 64, 3), 256, SMEM_MODE0>>>();
    scores_kernel<<<dim3(NTRI, 1, 4), 256, SMEM_MODE0>>>();
    softmax_kernel<<<BATCH * SEQ, 256>>>();
    pv_kernel<<<dim3(8, 16, 4), 256, SMEM_MODE1>>>(out);
}

// round 11
// speedup vs baseline: 1.2117x; 1.0352x over previous
#include <cuda_runtime.h>
#include <cstdint>

// ---------------------------------------------------------------------------
// CausalSelfAttention: B=4, S=2048, D=1024, fp32, causal softmax (scale 1/32)
// Staged: [round inputs] -> [proj x3] -> [scores lower-tri] -> [softmax] -> [PV]
// tf32 mma.sync m16n8k8, pre-rounded operands, 128x128 CTA tile, BK=32,
// 2-stage cp.async double buffer. 128 threads / 4 warps, warp tile 64x64
// (loads-per-MMA 1.0 vs 1.5 -> 33% less smem crossbar traffic).
// ---------------------------------------------------------------------------

#define BATCH 4
#define SEQ   2048
#define DIM   1024
#define NQT   (SEQ / 128)
#define NTRI  (NQT * (NQT + 1) / 2)   // 136 lower-tri tiles

__device__ float g_X [(size_t)BATCH * SEQ * DIM];
__device__ float g_Wq[(size_t)DIM * DIM];
__device__ float g_Wk[(size_t)DIM * DIM];
__device__ float g_Wv[(size_t)DIM * DIM];
__device__ float g_Q [(size_t)BATCH * SEQ * DIM];
__device__ float g_K [(size_t)BATCH * SEQ * DIM];
__device__ float g_V [(size_t)BATCH * SEQ * DIM];
__device__ float g_S [(size_t)BATCH * SEQ * SEQ];

// ---------------------------------------------------------------------------
__device__ __forceinline__ uint32_t f2tf32(float f) {
    uint32_t u;
    asm("cvt.rna.tf32.f32 %0, %1;" : "=r"(u) : "f"(f));
    return u;
}
__device__ __forceinline__ float roundtf(float f) {
    return __uint_as_float(f2tf32(f));
}

__device__ __forceinline__ void mma_tf32(float* d, const uint32_t* a,
                                         const uint32_t* b, const float* c) {
    asm volatile(
        "mma.sync.aligned.m16n8k8.row.col.f32.tf32.tf32.f32 "
        "{%0,%1,%2,%3}, {%4,%5,%6,%7}, {%8,%9}, {%10,%11,%12,%13};\n"
        : "=f"(d[0]), "=f"(d[1]), "=f"(d[2]), "=f"(d[3])
        : "r"(a[0]), "r"(a[1]), "r"(a[2]), "r"(a[3]),
          "r"(b[0]), "r"(b[1]),
          "f"(c[0]), "f"(c[1]), "f"(c[2]), "f"(c[3]));
}

__device__ __forceinline__ void cpa16(void* smem, const void* g) {
    uint32_t s = (uint32_t)__cvta_generic_to_shared(smem);
    asm volatile("cp.async.cg.shared.global [%0], [%1], 16;\n" :: "r"(s), "l"(g));
}
#define CP_COMMIT() asm volatile("cp.async.commit_group;\n")
#define CP_WAIT(n)  asm volatile("cp.async.wait_group %0;\n" :: "n"(n))

// ---------------------------------------------------------------------------
// 128x128 tile GEMM, BK=32, 2-stage double buffer, 128 threads.
// Warp grid 2(m) x 2(n); warp tile 64x64: mf=4 (16-row frags), nf=8 (8-col).
//   MODE 0: B stored [n][k] (k contig)  -> C = A @ B^T
//   MODE 1: B stored [k][n] (n contig)  -> C = A @ B
// ROUND 1: round C to tf32 on store.  kIters = K / 32.
// ---------------------------------------------------------------------------
template <int MODE, int ROUND>
__device__ __forceinline__ void gemm_core(const float* __restrict__ A,
                                          const float* __restrict__ Bm,
                                          float* __restrict__ C,
                                          int lda, int ldb, int ldc,
                                          int kIters, int row0, int col0) {
    constexpr int BM = 128, BK = 32;
    constexpr int BROWS = (MODE == 0) ? 128 : 32;
    constexpr int BCOLS = (MODE == 0) ? 32  : 128;
    constexpr int BPAD  = (MODE == 0) ? 4   : 8;
    constexpr int ASTR  = BK + 4;        // 36
    constexpr int BSTR  = BCOLS + BPAD;  // 36 / 136

    extern __shared__ float sm[];
    float* Asm = sm;                               // [2][BM][ASTR]
    float* Bsm = sm + (size_t)2 * BM * ASTR;       // [2][BROWS][BSTR]

    const int tid  = threadIdx.x;     // 0..127
    const int warp = tid >> 5;        // 0..3
    const int lane = tid & 31;
    const int wm   = (warp >> 1) * 64;   // 0 / 64
    const int wn   = (warp & 1) * 64;    // 0 / 64
    const int gid  = lane >> 2;
    const int tig  = lane & 3;

    float acc[4][8][4];
#pragma unroll
    for (int i = 0; i < 4; i++)
#pragma unroll
        for (int j = 0; j < 8; j++)
#pragma unroll
            for (int r = 0; r < 4; r++) acc[i][j][r] = 0.f;

    auto loadA = [&](int kt, int buf) {
#pragma unroll
        for (int i = 0; i < 8; i++) {          // 128x32 = 1024 16B chunks
            int f = tid + i * 128;
            int r = f >> 3, q = f & 7;
            cpa16(&Asm[((buf * BM + r) * ASTR) + q * 4],
                  &A[(size_t)(row0 + r) * lda + kt * BK + q * 4]);
        }
    };
    auto loadB = [&](int kt, int buf) {
        if (MODE == 0) {
#pragma unroll
            for (int i = 0; i < 8; i++) {
                int f = tid + i * 128;
                int r = f >> 3, q = f & 7;     // r = n, q*4 = k
                cpa16(&Bsm[((buf * BROWS + r) * BSTR) + q * 4],
                      &Bm[(size_t)(col0 + r) * ldb + kt * BK + q * 4]);
            }
        } else {
#pragma unroll
            for (int i = 0; i < 8; i++) {
                int f = tid + i * 128;
                int r = f >> 5, q = f & 31;    // r = k (0..31), q*4 = n
                cpa16(&Bsm[((buf * BROWS + r) * BSTR) + q * 4],
                      &Bm[(size_t)(kt * BK + r) * ldb + col0 + q * 4]);
            }
        }
    };

    loadA(0, 0);
    loadB(0, 0);
    CP_COMMIT();

    int buf = 0;
    for (int kt = 0; kt < kIters; kt++) {
        if (kt + 1 < kIters) {
            loadA(kt + 1, buf ^ 1);
            loadB(kt + 1, buf ^ 1);
            CP_COMMIT();
            CP_WAIT(1);
        } else {
            CP_WAIT(0);
        }
        __syncthreads();

#pragma unroll
        for (int ks = 0; ks < 4; ks++) {
            const int kk = ks * 8;
            uint32_t af[4][4];
#pragma unroll
            for (int mf = 0; mf < 4; mf++) {
                int r = wm + mf * 16 + gid;
                af[mf][0] = __float_as_uint(Asm[(buf * BM + r) * ASTR + kk + tig]);
                af[mf][1] = __float_as_uint(Asm[(buf * BM + r + 8) * ASTR + kk + tig]);
                af[mf][2] = __float_as_uint(Asm[(buf * BM + r) * ASTR + kk + tig + 4]);
                af[mf][3] = __float_as_uint(Asm[(buf * BM + r + 8) * ASTR + kk + tig + 4]);
            }
            uint32_t bf[8][2];
#pragma unroll
            for (int nf = 0; nf < 8; nf++) {
                int n = wn + nf * 8 + gid;
                if (MODE == 0) {
                    bf[nf][0] = __float_as_uint(Bsm[(buf * BROWS + n) * BSTR + kk + tig]);
                    bf[nf][1] = __float_as_uint(Bsm[(buf * BROWS + n) * BSTR + kk + tig + 4]);
                } else {
                    bf[nf][0] = __float_as_uint(Bsm[(buf * BROWS + kk + tig) * BSTR + n]);
                    bf[nf][1] = __float_as_uint(Bsm[(buf * BROWS + kk + tig + 4) * BSTR + n]);
                }
            }
#pragma unroll
            for (int mf = 0; mf < 4; mf++)
#pragma unroll
                for (int nf = 0; nf < 8; nf++)
                    mma_tf32(acc[mf][nf], af[mf], bf[nf], acc[mf][nf]);
        }
        __syncthreads();
        buf ^= 1;
    }

#pragma unroll
    for (int mf = 0; mf < 4; mf++) {
#pragma unroll
        for (int nf = 0; nf < 8; nf++) {
            int r = row0 + wm + mf * 16 + gid;
            int c = col0 + wn + nf * 8 + tig * 2;
            float v0 = acc[mf][nf][0], v1 = acc[mf][nf][1];
            float v2 = acc[mf][nf][2], v3 = acc[mf][nf][3];
            if (ROUND) { v0 = roundtf(v0); v1 = roundtf(v1);
                         v2 = roundtf(v2); v3 = roundtf(v3); }
            C[(size_t)r * ldc + c]           = v0;
            C[(size_t)r * ldc + c + 1]       = v1;
            C[(size_t)(r + 8) * ldc + c]     = v2;
            C[(size_t)(r + 8) * ldc + c + 1] = v3;
        }
    }
}

// smem bytes
#define SMEM_MODE0 (2 * (128 * 36 + 128 * 36) * 4)   // 73728
#define SMEM_MODE1 (2 * (128 * 36 + 32 * 136) * 4)   // 71680

// ---------------------------------------------------------------------------
// kernels
// ---------------------------------------------------------------------------
__global__ __launch_bounds__(256) void round_kernel(const float4* __restrict__ x,
                                                    const float4* __restrict__ wq,
                                                    const float4* __restrict__ wk,
                                                    const float4* __restrict__ wv) {
    const float4* src;
    float4* dst;
    int n4;
    switch (blockIdx.y) {
        case 0: src = x;  dst = (float4*)g_X;  n4 = BATCH * SEQ * DIM / 4; break;
        case 1: src = wq; dst = (float4*)g_Wq; n4 = DIM * DIM / 4; break;
        case 2: src = wk; dst = (float4*)g_Wk; n4 = DIM * DIM / 4; break;
        default: src = wv; dst = (float4*)g_Wv; n4 = DIM * DIM / 4; break;
    }
    for (int i = blockIdx.x * 256 + threadIdx.x; i < n4; i += gridDim.x * 256) {
        float4 v = src[i];
        v.x = roundtf(v.x); v.y = roundtf(v.y);
        v.z = roundtf(v.z); v.w = roundtf(v.w);
        dst[i] = v;
    }
}

__global__ __launch_bounds__(128) void proj_kernel() {
    const float* W = (blockIdx.z == 0) ? g_Wq : (blockIdx.z == 1) ? g_Wk : g_Wv;
    float* O = (blockIdx.z == 0) ? g_Q : (blockIdx.z == 1) ? g_K : g_V;
    gemm_core<0, 1>(g_X, W, O, DIM, DIM, DIM, DIM / 32,
                    blockIdx.y * 128, blockIdx.x * 128);
}

__device__ __forceinline__ void tri_decode(int t, int& qt, int& kt) {
    int q = (int)((sqrtf(8.0f * t + 1.0f) - 1.0f) * 0.5f);
    while ((q + 1) * (q + 2) / 2 <= t) q++;
    while (q * (q + 1) / 2 > t) q--;
    qt = q;
    kt = t - q * (q + 1) / 2;
}

__global__ __launch_bounds__(128) void scores_kernel() {
    int qt, kt;
    tri_decode(blockIdx.x, qt, kt);
    int b = blockIdx.z;
    const float* Qp = g_Q + (size_t)b * SEQ * DIM;
    const float* Kp = g_K + (size_t)b * SEQ * DIM;
    float* Sp = g_S + (size_t)b * SEQ * SEQ;
    gemm_core<0, 0>(Qp, Kp, Sp, DIM, DIM, SEQ, DIM / 32, qt * 128, kt * 128);
}

__global__ __launch_bounds__(256) void softmax_kernel() {
    const int row = blockIdx.x;
    const int b = row / SEQ, q = row % SEQ;
    float* p = g_S + (size_t)b * SEQ * SEQ + (size_t)q * SEQ;
    const int len  = q + 1;
    const int kend = ((q / 128) + 1) * 128;
    const float scale = 0.03125f;  // 1/sqrt(1024)

    __shared__ float red[8];
    __shared__ float red2[8];

    float vals[8];
    int cnt = 0;
    float m = -1e30f;
    for (int i = threadIdx.x; i < len; i += 256) {
        float v = p[i];
        vals[cnt++] = v;
        m = fmaxf(m, v);
    }
#pragma unroll
    for (int o = 16; o; o >>= 1) m = fmaxf(m, __shfl_xor_sync(~0u, m, o));
    if ((threadIdx.x & 31) == 0) red[threadIdx.x >> 5] = m;
    __syncthreads();
    m = red[0];
#pragma unroll
    for (int i = 1; i < 8; i++) m = fmaxf(m, red[i]);

    float s = 0.f;
#pragma unroll 8
    for (int j = 0; j < cnt; j++) {
        float e = __expf(scale * (vals[j] - m));
        vals[j] = e;
        s += e;
    }
#pragma unroll
    for (int o = 16; o; o >>= 1) s += __shfl_xor_sync(~0u, s, o);
    if ((threadIdx.x & 31) == 0) red2[threadIdx.x >> 5] = s;
    __syncthreads();
    s = 0.f;
#pragma unroll
    for (int i = 0; i < 8; i++) s += red2[i];
    const float inv = 1.0f / s;

    cnt = 0;
    for (int i = threadIdx.x; i < len; i += 256)
        p[i] = roundtf(vals[cnt++] * inv);
    for (int i = len + threadIdx.x; i < kend; i += 256) p[i] = 0.f;
}

__global__ __launch_bounds__(128) void pv_kernel(float* __restrict__ out) {
    int qt = blockIdx.y, et = blockIdx.x, b = blockIdx.z;
    const float* P = g_S + (size_t)b * SEQ * SEQ;
    const float* V = g_V + (size_t)b * SEQ * DIM;
    float* O = out + (size_t)b * SEQ * DIM;
    // causal: k range = (qt+1)*128 => kIters = (qt+1)*4 at BK=32
    gemm_core<1, 0>(P, V, O, SEQ, DIM, DIM, (qt + 1) * 4, qt * 128, et * 128);
}

// ---------------------------------------------------------------------------
extern "C" void kernel_launch(void* const* d_in, const int* in_sizes, int n_in,
                              void* d_out, int out_size) {
    int xi = 0;
    for (int i = 0; i < n_in; i++)
        if (in_sizes[i] == BATCH * SEQ * DIM) { xi = i; break; }
    const float* x = (const float*)d_in[xi];
    const float* w[3];
    int wi = 0;
    for (int i = 0; i < n_in && wi < 3; i++)
        if (i != xi) w[wi++] = (const float*)d_in[i];
    float* out = (float*)d_out;

    cudaFuncSetAttribute(proj_kernel,
                         cudaFuncAttributeMaxDynamicSharedMemorySize, SMEM_MODE0);
    cudaFuncSetAttribute(scores_kernel,
                         cudaFuncAttributeMaxDynamicSharedMemorySize, SMEM_MODE0);
    cudaFuncSetAttribute(pv_kernel,
                         cudaFuncAttributeMaxDynamicSharedMemorySize, SMEM_MODE1);

    round_kernel<<<dim3(512, 4), 256>>>((const float4*)x, (const float4*)w[0],
                                        (const float4*)w[1], (const float4*)w[2]);
    proj_kernel<<<dim3(8, 64, 3), 128, SMEM_MODE0>>>();
    scores_kernel<<<dim3(NTRI, 1, 4), 128, SMEM_MODE0>>>();
    softmax_kernel<<<BATCH * SEQ, 256>>>();
    pv_kernel<<<dim3(8, 16, 4), 128, SMEM_MODE1>>>(out);
}

// round 12
// speedup vs baseline: 2.2819x; 1.8833x over previous
#include <cuda_runtime.h>
#include <cuda_fp16.h>
#include <cstdint>

// ---------------------------------------------------------------------------
// CausalSelfAttention: B=4, S=2048, D=1024, fp32, causal softmax (scale 1/32)
// Pipeline: [cvt inputs->fp16] -> [proj Q,K,Vt] -> [scores lower-tri] ->
//           [softmax -> fp16 P] -> [PV -> out]
// All GEMMs: fp16 mma.sync m16n8k16 (f32 accum). fp16 mantissa == tf32
// mantissa (10 bits) -> same numerics as the tf32 path, 2x the pace.
// All GEMM operands k-major (V stored transposed), single-mode core.
// 128x128 CTA tile, BK=64 halves, 2-stage cp.async, 4 warps @ 64x64.
// ---------------------------------------------------------------------------

#define BATCH 4
#define SEQ   2048
#define DIM   1024
#define NQT   (SEQ / 128)
#define NTRI  (NQT * (NQT + 1) / 2)   // 136 lower-tri tiles

__device__ __align__(256) __half g_Xh [(size_t)BATCH * SEQ * DIM];
__device__ __align__(256) __half g_Wqh[(size_t)DIM * DIM];
__device__ __align__(256) __half g_Wkh[(size_t)DIM * DIM];
__device__ __align__(256) __half g_Wvh[(size_t)DIM * DIM];
__device__ __align__(256) __half g_Qh [(size_t)BATCH * SEQ * DIM];
__device__ __align__(256) __half g_Kh [(size_t)BATCH * SEQ * DIM];
__device__ __align__(256) __half g_Vth[(size_t)BATCH * DIM * SEQ]; // [b][e][k]
__device__ __align__(256) float  g_S  [(size_t)BATCH * SEQ * SEQ];
__device__ __align__(256) __half g_Ph [(size_t)BATCH * SEQ * SEQ];

// ---------------------------------------------------------------------------
__device__ __forceinline__ void mma_f16(float* d, const uint32_t* a,
                                        const uint32_t* b, const float* c) {
    asm volatile(
        "mma.sync.aligned.m16n8k16.row.col.f32.f16.f16.f32 "
        "{%0,%1,%2,%3}, {%4,%5,%6,%7}, {%8,%9}, {%10,%11,%12,%13};\n"
        : "=f"(d[0]), "=f"(d[1]), "=f"(d[2]), "=f"(d[3])
        : "r"(a[0]), "r"(a[1]), "r"(a[2]), "r"(a[3]),
          "r"(b[0]), "r"(b[1]),
          "f"(c[0]), "f"(c[1]), "f"(c[2]), "f"(c[3]));
}

__device__ __forceinline__ void cpa16(void* smem, const void* g) {
    uint32_t s = (uint32_t)__cvta_generic_to_shared(smem);
    asm volatile("cp.async.cg.shared.global [%0], [%1], 16;\n" :: "r"(s), "l"(g));
}
#define CP_COMMIT() asm volatile("cp.async.commit_group;\n")
#define CP_WAIT(n)  asm volatile("cp.async.wait_group %0;\n" :: "n"(n))

// ---------------------------------------------------------------------------
// fp16 GEMM core: C[128x128] tile = A[128,K] @ B[128,K]^T, both k-major.
// BK=64 halves (128B rows), 2-stage double buffer, 128 threads, warp 64x64.
// EPI 0: fp32 store to Cf.  EPI 1: fp16 store to Ch.  EPI 2: fp16 transposed
// store to Ch (Ch[(col)*ldc + row]).
// ---------------------------------------------------------------------------
template <int EPI>
__device__ __forceinline__ void gemm_fp16(const __half* __restrict__ A,
                                          const __half* __restrict__ B,
                                          float* __restrict__ Cf,
                                          __half* __restrict__ Ch,
                                          int lda, int ldb, int ldc,
                                          int kIters, int row0, int col0,
                                          int row0c) {
    constexpr int BM = 128, BK = 64, STR = 72;   // halves; 144B rows (16B mult)

    extern __shared__ __half smh[];
    __half* As = smh;                            // [2][128][72]
    __half* Bs = smh + (size_t)2 * BM * STR;     // [2][128][72]

    const int tid  = threadIdx.x;     // 0..127
    const int warp = tid >> 5;        // 0..3
    const int lane = tid & 31;
    const int wm   = (warp >> 1) * 64;
    const int wn   = (warp & 1) * 64;
    const int gid  = lane >> 2;       // 0..7
    const int tig  = lane & 3;        // 0..3

    float acc[4][8][4];
#pragma unroll
    for (int i = 0; i < 4; i++)
#pragma unroll
        for (int j = 0; j < 8; j++)
#pragma unroll
            for (int r = 0; r < 4; r++) acc[i][j][r] = 0.f;

    auto loadA = [&](int kt, int buf) {
#pragma unroll
        for (int i = 0; i < 8; i++) {            // 128 rows x 8 16B-chunks
            int f = tid + i * 128;
            int r = f >> 3, q = f & 7;
            cpa16(&As[((size_t)(buf * BM + r)) * STR + q * 8],
                  &A[(size_t)(row0 + r) * lda + kt * BK + q * 8]);
        }
    };
    auto loadB = [&](int kt, int buf) {
#pragma unroll
        for (int i = 0; i < 8; i++) {
            int f = tid + i * 128;
            int r = f >> 3, q = f & 7;
            cpa16(&Bs[((size_t)(buf * BM + r)) * STR + q * 8],
                  &B[(size_t)(col0 + r) * ldb + kt * BK + q * 8]);
        }
    };

    loadA(0, 0);
    loadB(0, 0);
    CP_COMMIT();

    int buf = 0;
    for (int kt = 0; kt < kIters; kt++) {
        if (kt + 1 < kIters) {
            loadA(kt + 1, buf ^ 1);
            loadB(kt + 1, buf ^ 1);
            CP_COMMIT();
            CP_WAIT(1);
        } else {
            CP_WAIT(0);
        }
        __syncthreads();

#pragma unroll
        for (int ks = 0; ks < 4; ks++) {         // 4 x K=16 per 64-k tile
            const int kk = ks * 16;
            uint32_t af[4][4];
#pragma unroll
            for (int mf = 0; mf < 4; mf++) {
                const __half* a0 = &As[((size_t)(buf * BM + wm + mf * 16 + gid)) * STR + kk + 2 * tig];
                const __half* a1 = a0 + 8 * STR;  // row +8
                af[mf][0] = *(const uint32_t*)a0;
                af[mf][1] = *(const uint32_t*)a1;
                af[mf][2] = *(const uint32_t*)(a0 + 8);
                af[mf][3] = *(const uint32_t*)(a1 + 8);
            }
            uint32_t bf[8][2];
#pragma unroll
            for (int nf = 0; nf < 8; nf++) {
                const __half* b0 = &Bs[((size_t)(buf * BM + wn + nf * 8 + gid)) * STR + kk + 2 * tig];
                bf[nf][0] = *(const uint32_t*)b0;
                bf[nf][1] = *(const uint32_t*)(b0 + 8);
            }
#pragma unroll
            for (int mf = 0; mf < 4; mf++)
#pragma unroll
                for (int nf = 0; nf < 8; nf++)
                    mma_f16(acc[mf][nf], af[mf], bf[nf], acc[mf][nf]);
        }
        __syncthreads();
        buf ^= 1;
    }

#pragma unroll
    for (int mf = 0; mf < 4; mf++) {
#pragma unroll
        for (int nf = 0; nf < 8; nf++) {
            int r = row0c + wm + mf * 16 + gid;
            int c = col0 + wn + nf * 8 + tig * 2;
            float v0 = acc[mf][nf][0], v1 = acc[mf][nf][1];
            float v2 = acc[mf][nf][2], v3 = acc[mf][nf][3];
            if (EPI == 0) {
                Cf[(size_t)r * ldc + c]           = v0;
                Cf[(size_t)r * ldc + c + 1]       = v1;
                Cf[(size_t)(r + 8) * ldc + c]     = v2;
                Cf[(size_t)(r + 8) * ldc + c + 1] = v3;
            } else if (EPI == 1) {
                *(__half2*)&Ch[(size_t)r * ldc + c]       = __floats2half2_rn(v0, v1);
                *(__half2*)&Ch[(size_t)(r + 8) * ldc + c] = __floats2half2_rn(v2, v3);
            } else {  // transposed: Ch[e][k] = C[k][e]
                Ch[(size_t)c * ldc + r]           = __float2half(v0);
                Ch[(size_t)(c + 1) * ldc + r]     = __float2half(v1);
                Ch[(size_t)c * ldc + r + 8]       = __float2half(v2);
                Ch[(size_t)(c + 1) * ldc + r + 8] = __float2half(v3);
            }
        }
    }
}

#define SMEM_GEMM (4 * 128 * 72 * 2)   // 73728 bytes

// ---------------------------------------------------------------------------
// kernels
// ---------------------------------------------------------------------------
__global__ __launch_bounds__(256) void cvt_kernel(const float4* __restrict__ x,
                                                  const float4* __restrict__ wq,
                                                  const float4* __restrict__ wk,
                                                  const float4* __restrict__ wv) {
    const float4* src;
    __half2* dst;
    int n4;
    switch (blockIdx.y) {
        case 0: src = x;  dst = (__half2*)g_Xh;  n4 = BATCH * SEQ * DIM / 4; break;
        case 1: src = wq; dst = (__half2*)g_Wqh; n4 = DIM * DIM / 4; break;
        case 2: src = wk; dst = (__half2*)g_Wkh; n4 = DIM * DIM / 4; break;
        default: src = wv; dst = (__half2*)g_Wvh; n4 = DIM * DIM / 4; break;
    }
    for (int i = blockIdx.x * 256 + threadIdx.x; i < n4; i += gridDim.x * 256) {
        float4 v = src[i];
        dst[i * 2]     = __floats2half2_rn(v.x, v.y);
        dst[i * 2 + 1] = __floats2half2_rn(v.z, v.w);
    }
}

__global__ __launch_bounds__(128) void proj_kernel() {
    const int z = blockIdx.z;
    const int row0 = blockIdx.y * 128;
    const int col0 = blockIdx.x * 128;
    if (z == 0) {
        gemm_fp16<1>(g_Xh, g_Wqh, nullptr, g_Qh, DIM, DIM, DIM, 16,
                     row0, col0, row0);
    } else if (z == 1) {
        gemm_fp16<1>(g_Xh, g_Wkh, nullptr, g_Kh, DIM, DIM, DIM, 16,
                     row0, col0, row0);
    } else {  // V: store transposed per batch -> g_Vth[b][e][k]
        const int b = row0 / SEQ;
        gemm_fp16<2>(g_Xh, g_Wvh, nullptr, g_Vth + (size_t)b * DIM * SEQ,
                     DIM, DIM, SEQ, 16, row0, col0, row0 % SEQ);
    }
}

__device__ __forceinline__ void tri_decode(int t, int& qt, int& kt) {
    int q = (int)((sqrtf(8.0f * t + 1.0f) - 1.0f) * 0.5f);
    while ((q + 1) * (q + 2) / 2 <= t) q++;
    while (q * (q + 1) / 2 > t) q--;
    qt = q;
    kt = t - q * (q + 1) / 2;
}

__global__ __launch_bounds__(128) void scores_kernel() {
    int qt, kt;
    tri_decode(blockIdx.x, qt, kt);
    int b = blockIdx.z;
    gemm_fp16<0>(g_Qh + (size_t)b * SEQ * DIM, g_Kh + (size_t)b * SEQ * DIM,
                 g_S + (size_t)b * SEQ * SEQ, nullptr,
                 DIM, DIM, SEQ, 16, qt * 128, kt * 128, qt * 128);
}

__global__ __launch_bounds__(256) void softmax_kernel() {
    const int row = blockIdx.x;
    const int b = row / SEQ, q = row % SEQ;
    const float* p = g_S + (size_t)b * SEQ * SEQ + (size_t)q * SEQ;
    __half* ph = g_Ph + (size_t)b * SEQ * SEQ + (size_t)q * SEQ;
    const int len  = q + 1;
    const int kend = ((q / 128) + 1) * 128;   // PV reads k < (qt+1)*128
    const float scale = 0.03125f;             // 1/sqrt(1024)

    __shared__ float red[8];
    __shared__ float red2[8];

    float vals[8];
    int cnt = 0;
    float m = -1e30f;
    for (int i = threadIdx.x; i < len; i += 256) {
        float v = p[i];
        vals[cnt++] = v;
        m = fmaxf(m, v);
    }
#pragma unroll
    for (int o = 16; o; o >>= 1) m = fmaxf(m, __shfl_xor_sync(~0u, m, o));
    if ((threadIdx.x & 31) == 0) red[threadIdx.x >> 5] = m;
    __syncthreads();
    m = red[0];
#pragma unroll
    for (int i = 1; i < 8; i++) m = fmaxf(m, red[i]);

    float s = 0.f;
#pragma unroll 8
    for (int j = 0; j < cnt; j++) {
        float e = __expf(scale * (vals[j] - m));
        vals[j] = e;
        s += e;
    }
#pragma unroll
    for (int o = 16; o; o >>= 1) s += __shfl_xor_sync(~0u, s, o);
    if ((threadIdx.x & 31) == 0) red2[threadIdx.x >> 5] = s;
    __syncthreads();
    s = 0.f;
#pragma unroll
    for (int i = 0; i < 8; i++) s += red2[i];
    const float inv = 1.0f / s;

    cnt = 0;
    for (int i = threadIdx.x; i < len; i += 256)
        ph[i] = __float2half(vals[cnt++] * inv);
    for (int i = len + threadIdx.x; i < kend; i += 256)
        ph[i] = __float2half(0.f);
}

__global__ __launch_bounds__(128) void pv_kernel(float* __restrict__ out) {
    int qt = blockIdx.y, et = blockIdx.x, b = blockIdx.z;
    // causal: k range = (qt+1)*128 => kIters = (qt+1)*2 at BK=64
    gemm_fp16<0>(g_Ph + (size_t)b * SEQ * SEQ, g_Vth + (size_t)b * DIM * SEQ,
                 out + (size_t)b * SEQ * DIM, nullptr,
                 SEQ, SEQ, DIM, (qt + 1) * 2, qt * 128, et * 128, qt * 128);
}

// ---------------------------------------------------------------------------
extern "C" void kernel_launch(void* const* d_in, const int* in_sizes, int n_in,
                              void* d_out, int out_size) {
    int xi = 0;
    for (int i = 0; i < n_in; i++)
        if (in_sizes[i] == BATCH * SEQ * DIM) { xi = i; break; }
    const float* x = (const float*)d_in[xi];
    const float* w[3];
    int wi = 0;
    for (int i = 0; i < n_in && wi < 3; i++)
        if (i != xi) w[wi++] = (const float*)d_in[i];
    float* out = (float*)d_out;

    cudaFuncSetAttribute(proj_kernel,
                         cudaFuncAttributeMaxDynamicSharedMemorySize, SMEM_GEMM);
    cudaFuncSetAttribute(scores_kernel,
                         cudaFuncAttributeMaxDynamicSharedMemorySize, SMEM_GEMM);
    cudaFuncSetAttribute(pv_kernel,
                         cudaFuncAttributeMaxDynamicSharedMemorySize, SMEM_GEMM);

    cvt_kernel<<<dim3(512, 4), 256>>>((const float4*)x, (const float4*)w[0],
                                      (const float4*)w[1], (const float4*)w[2]);
    proj_kernel<<<dim3(8, 64, 3), 128, SMEM_GEMM>>>();
    scores_kernel<<<dim3(NTRI, 1, 4), 128, SMEM_GEMM>>>();
    softmax_kernel<<<BATCH * SEQ, 256>>>();
    pv_kernel<<<dim3(8, 16, 4), 128, SMEM_GEMM>>>(out);
}